// round 13
// baseline (speedup 1.0000x reference)
#include <cuda_runtime.h>
#include <cuda_fp16.h>
#include <cstdint>

#define NBUS   4096
#define BATCH  64
#define XROWS  192        // c | s | c+s  (3 groups of 64)
#define KX     4096       // K dimension (bus index j)
#define BN     128
#define BK     32         // K per unit
#define NCTA   148
#define NTILES 32
#define KUNITS 128
#define NUNITS (NTILES * KUNITS)   // 4096
#define NSTAGES 3
#define THREADS 512               // 12 consumer warps + 4 producer warps

#define HSTRIDE 40                         // halves per padded row (80 B)
#define STAGE_A   (XROWS * HSTRIDE * 2)    // 15360 : fp16 X tile 192 x 32
#define TILE16    (BN * HSTRIDE * 2)       // 10240 : one fp16 operand tile
#define STAGE_B3  (3 * TILE16)             // 30720 : G16 | B16 | D16
#define STAGE_BYTES (STAGE_A + STAGE_B3)   // 46080
#define SMEM_TOTAL  (NSTAGES * STAGE_BYTES)// 138240

#define BAR_CNT 512
// named barriers: FULL[s]=1+s (1..3), FREE[s]=4+s (4..6)

// Scratch (no runtime allocation allowed)
__device__ __half  g_X16[XROWS * KX];            // 1.5 MB
__device__ float   g_C[XROWS * NBUS];            // 3 MB p1|p2|p3 (atomic)
__device__ float2  g_trig[BATCH * NBUS];         // 2 MB cached (cos, sin)

// ---------------------------------------------------------------------------
// Kernel 1: build X rows (c, s, c+s fp16), cache trig, zero g_C
// ---------------------------------------------------------------------------
__global__ void prep_kernel(const float* __restrict__ Vm,
                            const float* __restrict__ Va) {
    int t = blockIdx.x * blockDim.x + threadIdx.x;   // over BATCH*NBUS/4 = 65536
    if (t >= BATCH * NBUS / 4) return;
    // zero accumulators: 786432 floats / 65536 threads = 3 float4 each
    *(float4*)&g_C[t * 12]     = make_float4(0.f, 0.f, 0.f, 0.f);
    *(float4*)&g_C[t * 12 + 4] = make_float4(0.f, 0.f, 0.f, 0.f);
    *(float4*)&g_C[t * 12 + 8] = make_float4(0.f, 0.f, 0.f, 0.f);

    int e = t * 4;
    int b = e >> 12;
    int j = e & (NBUS - 1);
    const float4 vm = *(const float4*)&Vm[e];
    const float4 va = *(const float4*)&Va[e];
    float vmv[4] = {vm.x, vm.y, vm.z, vm.w};
    float vav[4] = {va.x, va.y, va.z, va.w};
    __half hc[4], hs[4], hp[4];
    float2 tr[4];
#pragma unroll
    for (int q = 0; q < 4; ++q) {
        float sn, cs;
        __sincosf(vav[q], &sn, &cs);
        tr[q] = make_float2(cs, sn);
        float c = vmv[q] * cs, s = vmv[q] * sn;
        hc[q] = __float2half_rn(c);
        hs[q] = __float2half_rn(s);
        hp[q] = __float2half_rn(c + s);
    }
    *(uint2*)&g_X16[b * KX + j]            = *(uint2*)hc;   // group 0: c
    *(uint2*)&g_X16[(64 + b) * KX + j]     = *(uint2*)hs;   // group 1: s
    *(uint2*)&g_X16[(128 + b) * KX + j]    = *(uint2*)hp;   // group 2: c+s
    *(float4*)&g_trig[e]     = make_float4(tr[0].x, tr[0].y, tr[1].x, tr[1].y);
    *(float4*)&g_trig[e + 2] = make_float4(tr[2].x, tr[2].y, tr[3].x, tr[3].y);
}

// ---------------------------------------------------------------------------
__device__ __forceinline__ void cp16(uint32_t saddr, const void* gptr) {
    asm volatile("cp.async.cg.shared.global [%0], [%1], 16;\n"
                 :: "r"(saddr), "l"(gptr));
}
__device__ __forceinline__ void bar_sync(int id) {
    asm volatile("bar.sync %0, %1;" :: "r"(id), "n"(BAR_CNT) : "memory");
}
__device__ __forceinline__ void bar_arrive(int id) {
    asm volatile("bar.arrive %0, %1;" :: "r"(id), "n"(BAR_CNT) : "memory");
}
#define LDSM4(r0, r1, r2, r3, addr)                                           \
    asm volatile("ldmatrix.sync.aligned.m8n8.x4.shared.b16 "                  \
                 "{%0,%1,%2,%3}, [%4];"                                       \
                 : "=r"(r0), "=r"(r1), "=r"(r2), "=r"(r3) : "r"(addr))

// ---------------------------------------------------------------------------
// Persistent warp-specialized 3M-complex fp16 GEMM over 4096 (nt, kt) units.
//   p1 = c*G^T, p2 = s*B^T, p3 = (c+s)*(G-B)^T   (each M=64, N=128, K=32/unit)
//   warps 0-11 : consumers (g = w%3 group; wn = w/3 N-slice)
//   warps 12-15: producers (cp.async A ring; LDG G,B -> regs -> G16,B16,D16)
// ---------------------------------------------------------------------------
__global__ void __launch_bounds__(THREADS)
gemm_kernel(const float* __restrict__ Gm, const float* __restrict__ Bm) {
    extern __shared__ char smem[];
    uint32_t sbase;
    asm("{ .reg .u64 t; cvta.to.shared.u64 t, %1; cvt.u32.u64 %0, t; }"
        : "=r"(sbase) : "l"(smem));

    const int tid  = threadIdx.x;
    const int lane = tid & 31;
    const int warp = tid >> 5;

    const int start = (int)(((long long)blockIdx.x * NUNITS) / NCTA);
    const int end   = (int)(((long long)(blockIdx.x + 1) * NUNITS) / NCTA);

    if (warp >= 12) {
        // ================= PRODUCER =================
        const int ptid = tid - 384;   // 0..127

        float4 gq[8], bq[8];          // single-buffer LDG registers (G, B)

        auto ldgGB = [&](int u) {
            const int nt = u >> 7;
            const int kt = u & 127;
            const int n0  = nt * BN;
            const int kbx = kt * BK;
#pragma unroll
            for (int it = 0; it < 8; ++it) {
                int v   = ptid + it * 128;
                int row = v >> 3;
                int c   = v & 7;
                gq[it] = *(const float4*)&Gm[(size_t)(n0 + row) * NBUS + kbx + c * 4];
                bq[it] = *(const float4*)&Bm[(size_t)(n0 + row) * NBUS + kbx + c * 4];
            }
        };
        auto convert = [&](int u) {
            const int s3 = u % 3;
            __half* t16 = (__half*)(smem + s3 * STAGE_BYTES + STAGE_A);
            __half* g16 = t16;
            __half* b16 = t16 + TILE16 / 2;
            __half* d16 = t16 + TILE16;
#pragma unroll
            for (int it = 0; it < 8; ++it) {
                int v   = ptid + it * 128;
                int row = v >> 3;
                int k   = (v & 7) * 4;
                int off = row * HSTRIDE + k;
                float4 g = gq[it];
                float4 b = bq[it];
                __half2 h0, h1;
                uint2 pk;
                h0 = __floats2half2_rn(g.x, g.y);
                h1 = __floats2half2_rn(g.z, g.w);
                pk.x = *(uint32_t*)&h0; pk.y = *(uint32_t*)&h1;
                *(uint2*)(g16 + off) = pk;
                h0 = __floats2half2_rn(b.x, b.y);
                h1 = __floats2half2_rn(b.z, b.w);
                pk.x = *(uint32_t*)&h0; pk.y = *(uint32_t*)&h1;
                *(uint2*)(b16 + off) = pk;
                h0 = __floats2half2_rn(g.x - b.x, g.y - b.y);
                h1 = __floats2half2_rn(g.z - b.z, g.w - b.w);
                pk.x = *(uint32_t*)&h0; pk.y = *(uint32_t*)&h1;
                *(uint2*)(d16 + off) = pk;
            }
        };
        auto issueA = [&](int u) {
            const int s3  = u % 3;
            const int kbx = (u & 127) * BK;
            const uint32_t sA = sbase + (uint32_t)s3 * STAGE_BYTES;
#pragma unroll
            for (int it = 0; it < 6; ++it) {   // 768 x 16B : A tile 192x32
                int v   = ptid + it * 128;
                int row = v >> 2;
                int c   = v & 3;
                cp16(sA + (uint32_t)(row * 80 + c * 16),
                     (const void*)&g_X16[(size_t)row * KX + kbx + c * 8]);
            }
        };

        // prologue
        ldgGB(start);
        issueA(start);
        asm volatile("cp.async.commit_group;");
        if (start + 1 < end) {
            issueA(start + 1);
            asm volatile("cp.async.commit_group;");
        }

        for (int u = start; u < end; ++u) {
            if (u + 2 < end) {
                if ((u + 2) - start >= NSTAGES)
                    bar_sync(4 + (u + 2) % 3);           // FREE[s3(u+2)]
                issueA(u + 2);
                asm volatile("cp.async.commit_group;");
            }
            // A(u) completion
            if (u + 2 < end)      asm volatile("cp.async.wait_group 2;");
            else if (u + 1 < end) asm volatile("cp.async.wait_group 1;");
            else                  asm volatile("cp.async.wait_group 0;");

            convert(u);                                  // regs -> fp16 tiles
            bar_arrive(1 + u % 3);                       // FULL[s3(u)]
            if (u + 1 < end) ldgGB(u + 1);               // prefetch next
        }
    } else {
        // ================= CONSUMER =================
        const int g  = warp % 3;    // group: 0=c*G, 1=s*B, 2=(c+s)*D
        const int wn = warp / 3;    // 4 N-slices of 32 cols
        const int lm = lane >> 3;
        const int l8 = lane & 7;

        uint32_t aoff[4], boff[2];
#pragma unroll
        for (int mi = 0; mi < 4; ++mi) {
            int row = g * 64 + mi * 16 + ((lm & 1) << 3) + l8;
            aoff[mi] = (uint32_t)(row * HSTRIDE + ((lm >> 1) << 3)) * 2u;
        }
#pragma unroll
        for (int np = 0; np < 2; ++np) {
            int n = wn * 32 + np * 16 + ((lm >> 1) << 3) + l8;
            boff[np] = (uint32_t)(n * HSTRIDE + ((lm & 1) << 3)) * 2u
                     + (uint32_t)(STAGE_A + g * TILE16);
        }

        float acc[4][4][4];
#pragma unroll
        for (int mi = 0; mi < 4; ++mi)
#pragma unroll
            for (int ni = 0; ni < 4; ++ni)
#pragma unroll
                for (int q = 0; q < 4; ++q) acc[mi][ni][q] = 0.f;

        const int gid = lane >> 2;
        const int tig = lane & 3;

        auto flush = [&](int nt) {
            const int n0 = nt * BN;
#pragma unroll
            for (int mi = 0; mi < 4; ++mi) {
                int r0 = g * 64 + mi * 16 + gid;
#pragma unroll
                for (int ni = 0; ni < 4; ++ni) {
                    int col = n0 + wn * 32 + ni * 8 + tig * 2;
                    atomicAdd(&g_C[(size_t)r0 * NBUS + col],       acc[mi][ni][0]);
                    atomicAdd(&g_C[(size_t)r0 * NBUS + col + 1],   acc[mi][ni][1]);
                    atomicAdd(&g_C[(size_t)(r0 + 8) * NBUS + col],     acc[mi][ni][2]);
                    atomicAdd(&g_C[(size_t)(r0 + 8) * NBUS + col + 1], acc[mi][ni][3]);
                    acc[mi][ni][0] = 0.f; acc[mi][ni][1] = 0.f;
                    acc[mi][ni][2] = 0.f; acc[mi][ni][3] = 0.f;
                }
            }
        };

        int cur_nt = start >> 7;
        int s3 = start % 3;
        for (int u = start; u < end; ++u) {
            bar_sync(1 + s3);                            // FULL[s3]
            const uint32_t sA16 = sbase + (uint32_t)s3 * STAGE_BYTES;

#pragma unroll
            for (int kk = 0; kk < 2; ++kk) {
                const uint32_t kbyte = kk * 32;   // 16 halves
                uint32_t a[4][4], bb[4][2];
#pragma unroll
                for (int mi = 0; mi < 4; ++mi)
                    LDSM4(a[mi][0], a[mi][1], a[mi][2], a[mi][3],
                          sA16 + aoff[mi] + kbyte);
#pragma unroll
                for (int np = 0; np < 2; ++np)
                    LDSM4(bb[np * 2][0], bb[np * 2][1],
                          bb[np * 2 + 1][0], bb[np * 2 + 1][1],
                          sA16 + boff[np] + kbyte);
                if (kk == 1) bar_arrive(4 + s3);        // FREE[s3]
#pragma unroll
                for (int mi = 0; mi < 4; ++mi)
#pragma unroll
                    for (int ni = 0; ni < 4; ++ni)
                        asm volatile(
                            "mma.sync.aligned.m16n8k16.row.col.f32.f16.f16.f32 "
                            "{%0,%1,%2,%3}, {%4,%5,%6,%7}, {%8,%9}, {%0,%1,%2,%3};"
                            : "+f"(acc[mi][ni][0]), "+f"(acc[mi][ni][1]),
                              "+f"(acc[mi][ni][2]), "+f"(acc[mi][ni][3])
                            : "r"(a[mi][0]), "r"(a[mi][1]),
                              "r"(a[mi][2]), "r"(a[mi][3]),
                              "r"(bb[ni][0]), "r"(bb[ni][1]));
            }

            if (u == end - 1 || ((u + 1) >> 7) != cur_nt) {
                flush(cur_nt);
                cur_nt = (u + 1) >> 7;
            }
            s3 = (s3 + 1 == 3) ? 0 : s3 + 1;
        }
    }
}

// ---------------------------------------------------------------------------
// epilogue: U = p1 + p2 ; W = p3 - p1 + p2
// ---------------------------------------------------------------------------
__global__ void epilogue_kernel(const float* __restrict__ Vm,
                                const float* __restrict__ Pin,
                                const float* __restrict__ Qin,
                                float* __restrict__ out) {
    int idx = blockIdx.x * blockDim.x + threadIdx.x;   // over BATCH*NBUS/2
    if (idx >= BATCH * NBUS / 2) return;
    int e = idx * 2;
    int b = e >> 12;
    int i = e & (NBUS - 1);

    const float2 p1 = *(const float2*)&g_C[(size_t)b * NBUS + i];
    const float2 p2 = *(const float2*)&g_C[(size_t)(64 + b) * NBUS + i];
    const float2 p3 = *(const float2*)&g_C[(size_t)(128 + b) * NBUS + i];
    float2 U = make_float2(p1.x + p2.x, p1.y + p2.y);
    float2 W = make_float2(p3.x - p1.x + p2.x, p3.y - p1.y + p2.y);

    const float2 vm  = *(const float2*)&Vm[e];
    const float2 pin = *(const float2*)&Pin[e];
    const float2 qin = *(const float2*)&Qin[e];
    const float4 tr  = *(const float4*)&g_trig[e];   // cs0,sn0,cs1,sn1

    float2 rp, rq;
    rp.x = vm.x * (tr.x * U.x + tr.y * W.x) - pin.x;
    rq.x = vm.x * (tr.y * U.x - tr.x * W.x) - qin.x;
    rp.y = vm.y * (tr.z * U.y + tr.w * W.y) - pin.y;
    rq.y = vm.y * (tr.w * U.y - tr.z * W.y) - qin.y;

    *(float2*)&out[e]                = rp;
    *(float2*)&out[BATCH * NBUS + e] = rq;
}

// ---------------------------------------------------------------------------
extern "C" void kernel_launch(void* const* d_in, const int* in_sizes, int n_in,
                              void* d_out, int out_size) {
    const float* Vm  = (const float*)d_in[0];
    const float* Va  = (const float*)d_in[1];
    const float* Pin = (const float*)d_in[2];
    const float* Qin = (const float*)d_in[3];
    const float* Gm  = (const float*)d_in[4];
    const float* Bm  = (const float*)d_in[5];
    float* out = (float*)d_out;

    cudaFuncSetAttribute(gemm_kernel,
                         cudaFuncAttributeMaxDynamicSharedMemorySize, SMEM_TOTAL);

    prep_kernel<<<(BATCH * NBUS / 4 + 255) / 256, 256>>>(Vm, Va);
    gemm_kernel<<<NCTA, THREADS, SMEM_TOTAL>>>(Gm, Bm);
    epilogue_kernel<<<(BATCH * NBUS / 2 + 255) / 256, 256>>>(Vm, Pin, Qin, out);
}

// round 14
// speedup vs baseline: 1.1728x; 1.1728x over previous
#include <cuda_runtime.h>
#include <cuda_fp16.h>
#include <cstdint>

#define NBUS   4096
#define BATCH  64
#define XROWS  192        // c | s | c+s  (3 groups of 64)
#define KX     4096       // K dimension (bus index j)
#define BN     128
#define BK     32         // K per unit
#define NCTA   148
#define NTILES 32
#define KUNITS 128
#define NUNITS (NTILES * KUNITS)   // 4096
#define NSTAGES 3
#define THREADS 512               // 12 consumer warps + 4 producer warps

#define HSTRIDE 40                         // halves per padded row (80 B)
#define STAGE_A   (XROWS * HSTRIDE * 2)    // 15360 : fp16 X tile 192 x 32
#define TILE16    (BN * HSTRIDE * 2)       // 10240 : one fp16 operand tile
#define STAGE_B3  (3 * TILE16)             // 30720 : G16 | B16 | D16
#define STAGE_BYTES (STAGE_A + STAGE_B3)   // 46080
#define BF_OFF    (NSTAGES * STAGE_BYTES)  // 138240
#define BF_BYTES  32768                    // G f32 | B f32 staging
#define SMEM_TOTAL (BF_OFF + 2 * BF_BYTES) // 203776

#define BAR_CNT 512
// named barriers: FULL[s]=1+s (1..3), FREE[s]=4+s (4..6)

// Scratch (no runtime allocation allowed)
__device__ __half  g_X16[XROWS * KX];            // 1.5 MB
__device__ float   g_C[XROWS * NBUS];            // 3 MB p1|p2|p3 (atomic)
__device__ float2  g_trig[BATCH * NBUS];         // 2 MB cached (cos, sin)

// ---------------------------------------------------------------------------
// Kernel 1: build X rows (c, s, c+s fp16), cache trig, zero g_C
// 2 elems/thread (131072 threads) for latency hiding on the MUFU path
// ---------------------------------------------------------------------------
__global__ void prep_kernel(const float* __restrict__ Vm,
                            const float* __restrict__ Va) {
    int t = blockIdx.x * blockDim.x + threadIdx.x;   // over BATCH*NBUS/2 = 131072
    if (t >= BATCH * NBUS / 2) return;
    // zero accumulators: 786432 floats / 131072 threads = 6 floats each
    *(float2*)&g_C[t * 6]     = make_float2(0.f, 0.f);
    *(float2*)&g_C[t * 6 + 2] = make_float2(0.f, 0.f);
    *(float2*)&g_C[t * 6 + 4] = make_float2(0.f, 0.f);

    int e = t * 2;
    int b = e >> 12;
    int j = e & (NBUS - 1);
    const float2 vm = *(const float2*)&Vm[e];
    const float2 va = *(const float2*)&Va[e];
    float sn0, cs0, sn1, cs1;
    __sincosf(va.x, &sn0, &cs0);
    __sincosf(va.y, &sn1, &cs1);
    float c0 = vm.x * cs0, s0 = vm.x * sn0;
    float c1 = vm.y * cs1, s1 = vm.y * sn1;
    __half2 hc = __floats2half2_rn(c0, c1);
    __half2 hs = __floats2half2_rn(s0, s1);
    __half2 hp = __floats2half2_rn(c0 + s0, c1 + s1);
    *(uint32_t*)&g_X16[b * KX + j]         = *(uint32_t*)&hc;   // group 0: c
    *(uint32_t*)&g_X16[(64 + b) * KX + j]  = *(uint32_t*)&hs;   // group 1: s
    *(uint32_t*)&g_X16[(128 + b) * KX + j] = *(uint32_t*)&hp;   // group 2: c+s
    *(float4*)&g_trig[e] = make_float4(cs0, sn0, cs1, sn1);
}

// ---------------------------------------------------------------------------
__device__ __forceinline__ void cp16(uint32_t saddr, const void* gptr) {
    asm volatile("cp.async.cg.shared.global [%0], [%1], 16;\n"
                 :: "r"(saddr), "l"(gptr));
}
__device__ __forceinline__ void bar_sync(int id) {
    asm volatile("bar.sync %0, %1;" :: "r"(id), "n"(BAR_CNT) : "memory");
}
__device__ __forceinline__ void bar_arrive(int id) {
    asm volatile("bar.arrive %0, %1;" :: "r"(id), "n"(BAR_CNT) : "memory");
}
#define LDSM4(r0, r1, r2, r3, addr)                                           \
    asm volatile("ldmatrix.sync.aligned.m8n8.x4.shared.b16 "                  \
                 "{%0,%1,%2,%3}, [%4];"                                       \
                 : "=r"(r0), "=r"(r1), "=r"(r2), "=r"(r3) : "r"(addr))

// ---------------------------------------------------------------------------
// Persistent warp-specialized 3M-complex fp16 GEMM over 4096 (nt, kt) units.
//   p1 = c*G^T, p2 = s*B^T, p3 = (c+s)*(G-B)^T   (each M=64, N=128, K=32/unit)
//   warps 0-11 : consumers (g = w%3 selects group/operand; wn = w/3 N-slice)
//   warps 12-15: producers (cp.async A + G,B staging; convert -> G16,B16,D16)
// ---------------------------------------------------------------------------
__global__ void __launch_bounds__(THREADS)
gemm_kernel(const float* __restrict__ Gm, const float* __restrict__ Bm) {
    extern __shared__ char smem[];
    uint32_t sbase;
    asm("{ .reg .u64 t; cvta.to.shared.u64 t, %1; cvt.u32.u64 %0, t; }"
        : "=r"(sbase) : "l"(smem));

    const int tid  = threadIdx.x;
    const int lane = tid & 31;
    const int warp = tid >> 5;

    const int start = (int)(((long long)blockIdx.x * NUNITS) / NCTA);
    const int end   = (int)(((long long)(blockIdx.x + 1) * NUNITS) / NCTA);

    if (warp >= 12) {
        // ================= PRODUCER =================
        const int ptid = tid - 384;   // 0..127

        auto issue = [&](int u, int s3) {
            const int nt = u >> 7;            // /KUNITS
            const int kt = u & 127;
            const uint32_t sA  = sbase + (uint32_t)s3 * STAGE_BYTES;
            const uint32_t sBF = sbase + BF_OFF + (uint32_t)(u & 1) * BF_BYTES;
            const int n0  = nt * BN;
            const int kbx = kt * BK;
            // A tile: 192 rows x 32 halves = 768 x 16B
#pragma unroll
            for (int it = 0; it < 6; ++it) {
                int v   = ptid + it * 128;
                int row = v >> 2;
                int c   = v & 3;
                cp16(sA + (uint32_t)(row * 80 + c * 16),
                     (const void*)&g_X16[(size_t)row * KX + kbx + c * 8]);
            }
            // G then B f32 staging: each 128 rows x 32 f32 = 1024 x 16B
#pragma unroll
            for (int it = 0; it < 8; ++it) {
                int v   = ptid + it * 128;
                int row = v >> 3;
                int c   = v & 7;
                cp16(sBF + (uint32_t)(row * 128 + c * 16),
                     (const void*)&Gm[(size_t)(n0 + row) * NBUS + kbx + c * 4]);
            }
#pragma unroll
            for (int it = 0; it < 8; ++it) {
                int v   = ptid + it * 128;
                int row = v >> 3;
                int c   = v & 7;
                cp16(sBF + 16384u + (uint32_t)(row * 128 + c * 16),
                     (const void*)&Bm[(size_t)(n0 + row) * NBUS + kbx + c * 4]);
            }
        };
        auto convert = [&](int u, int s3) {
            const float* bfG = (const float*)(smem + BF_OFF + (u & 1) * BF_BYTES);
            const float* bfB = bfG + 4096;
            __half* t16 = (__half*)(smem + s3 * STAGE_BYTES + STAGE_A);
            __half* g16 = t16;                        // tile 0
            __half* b16 = t16 + TILE16 / 2;           // tile 1 (half elements)
            __half* d16 = t16 + TILE16;               // tile 2
#pragma unroll
            for (int p = 0; p < 8; ++p) {             // 8 x 128 x 4 = 4096 floats
                int e = (ptid + p * 128) * 4;         // 0..4092
                float4 g = *(const float4*)(bfG + e);
                float4 b = *(const float4*)(bfB + e);
                int row = e >> 5, k = e & 31;
                int off = row * HSTRIDE + k;
                __half2 h0, h1;
                uint2 pk;
                h0 = __floats2half2_rn(g.x, g.y);
                h1 = __floats2half2_rn(g.z, g.w);
                pk.x = *(uint32_t*)&h0; pk.y = *(uint32_t*)&h1;
                *(uint2*)(g16 + off) = pk;
                h0 = __floats2half2_rn(b.x, b.y);
                h1 = __floats2half2_rn(b.z, b.w);
                pk.x = *(uint32_t*)&h0; pk.y = *(uint32_t*)&h1;
                *(uint2*)(b16 + off) = pk;
                h0 = __floats2half2_rn(g.x - b.x, g.y - b.y);
                h1 = __floats2half2_rn(g.z - b.z, g.w - b.w);
                pk.x = *(uint32_t*)&h0; pk.y = *(uint32_t*)&h1;
                *(uint2*)(d16 + off) = pk;
            }
        };

        int s3 = start % 3;
        int p3prev = 0;
        for (int u = start; u < end; ++u) {
            if (u - start >= NSTAGES) bar_sync(4 + s3);   // FREE[s3(u)]
            issue(u, s3);
            asm volatile("cp.async.commit_group;");
            if (u > start) {
                asm volatile("cp.async.wait_group 1;");   // group(u-1) done
                convert(u - 1, p3prev);
                bar_arrive(1 + p3prev);                   // FULL[u-1]
            }
            p3prev = s3;
            s3 = (s3 + 1 == 3) ? 0 : s3 + 1;
        }
        asm volatile("cp.async.wait_group 0;");
        convert(end - 1, p3prev);
        bar_arrive(1 + p3prev);
    } else {
        // ================= CONSUMER =================
        const int g  = warp % 3;    // group: 0=c*G, 1=s*B, 2=(c+s)*D
        const int wn = warp / 3;    // 4 N-slices of 32 cols
        const int lm = lane >> 3;
        const int l8 = lane & 7;

        uint32_t aoff[4], boff[2];
#pragma unroll
        for (int mi = 0; mi < 4; ++mi) {
            int row = g * 64 + mi * 16 + ((lm & 1) << 3) + l8;
            aoff[mi] = (uint32_t)(row * HSTRIDE + ((lm >> 1) << 3)) * 2u;
        }
#pragma unroll
        for (int np = 0; np < 2; ++np) {
            int n = wn * 32 + np * 16 + ((lm >> 1) << 3) + l8;
            boff[np] = (uint32_t)(n * HSTRIDE + ((lm & 1) << 3)) * 2u
                     + (uint32_t)(STAGE_A + g * TILE16);
        }

        float acc[4][4][4];
#pragma unroll
        for (int mi = 0; mi < 4; ++mi)
#pragma unroll
            for (int ni = 0; ni < 4; ++ni)
#pragma unroll
                for (int q = 0; q < 4; ++q) acc[mi][ni][q] = 0.f;

        const int gid = lane >> 2;
        const int tig = lane & 3;

        auto flush = [&](int nt) {
            const int n0 = nt * BN;
#pragma unroll
            for (int mi = 0; mi < 4; ++mi) {
                int r0 = g * 64 + mi * 16 + gid;
#pragma unroll
                for (int ni = 0; ni < 4; ++ni) {
                    int col = n0 + wn * 32 + ni * 8 + tig * 2;
                    atomicAdd(&g_C[(size_t)r0 * NBUS + col],       acc[mi][ni][0]);
                    atomicAdd(&g_C[(size_t)r0 * NBUS + col + 1],   acc[mi][ni][1]);
                    atomicAdd(&g_C[(size_t)(r0 + 8) * NBUS + col],     acc[mi][ni][2]);
                    atomicAdd(&g_C[(size_t)(r0 + 8) * NBUS + col + 1], acc[mi][ni][3]);
                    acc[mi][ni][0] = 0.f; acc[mi][ni][1] = 0.f;
                    acc[mi][ni][2] = 0.f; acc[mi][ni][3] = 0.f;
                }
            }
        };

        int cur_nt = start >> 7;
        int s3 = start % 3;
        for (int u = start; u < end; ++u) {
            bar_sync(1 + s3);                            // FULL[s3]
            const uint32_t sA16 = sbase + (uint32_t)s3 * STAGE_BYTES;

#pragma unroll
            for (int kk = 0; kk < 2; ++kk) {
                const uint32_t kbyte = kk * 32;   // 16 halves
                uint32_t a[4][4], bb[4][2];
#pragma unroll
                for (int mi = 0; mi < 4; ++mi)
                    LDSM4(a[mi][0], a[mi][1], a[mi][2], a[mi][3],
                          sA16 + aoff[mi] + kbyte);
#pragma unroll
                for (int np = 0; np < 2; ++np)
                    LDSM4(bb[np * 2][0], bb[np * 2][1],
                          bb[np * 2 + 1][0], bb[np * 2 + 1][1],
                          sA16 + boff[np] + kbyte);
                if (kk == 1) bar_arrive(4 + s3);        // FREE[s3]
#pragma unroll
                for (int mi = 0; mi < 4; ++mi)
#pragma unroll
                    for (int ni = 0; ni < 4; ++ni)
                        asm volatile(
                            "mma.sync.aligned.m16n8k16.row.col.f32.f16.f16.f32 "
                            "{%0,%1,%2,%3}, {%4,%5,%6,%7}, {%8,%9}, {%0,%1,%2,%3};"
                            : "+f"(acc[mi][ni][0]), "+f"(acc[mi][ni][1]),
                              "+f"(acc[mi][ni][2]), "+f"(acc[mi][ni][3])
                            : "r"(a[mi][0]), "r"(a[mi][1]),
                              "r"(a[mi][2]), "r"(a[mi][3]),
                              "r"(bb[ni][0]), "r"(bb[ni][1]));
            }

            if (u == end - 1 || ((u + 1) >> 7) != cur_nt) {
                flush(cur_nt);
                cur_nt = (u + 1) >> 7;
            }
            s3 = (s3 + 1 == 3) ? 0 : s3 + 1;
        }
    }
}

// ---------------------------------------------------------------------------
// epilogue: U = p1 + p2 ; W = p3 - p1 + p2
// ---------------------------------------------------------------------------
__global__ void epilogue_kernel(const float* __restrict__ Vm,
                                const float* __restrict__ Pin,
                                const float* __restrict__ Qin,
                                float* __restrict__ out) {
    int idx = blockIdx.x * blockDim.x + threadIdx.x;   // over BATCH*NBUS/2
    if (idx >= BATCH * NBUS / 2) return;
    int e = idx * 2;
    int b = e >> 12;
    int i = e & (NBUS - 1);

    const float2 p1 = *(const float2*)&g_C[(size_t)b * NBUS + i];
    const float2 p2 = *(const float2*)&g_C[(size_t)(64 + b) * NBUS + i];
    const float2 p3 = *(const float2*)&g_C[(size_t)(128 + b) * NBUS + i];
    float2 U = make_float2(p1.x + p2.x, p1.y + p2.y);
    float2 W = make_float2(p3.x - p1.x + p2.x, p3.y - p1.y + p2.y);

    const float2 vm  = *(const float2*)&Vm[e];
    const float2 pin = *(const float2*)&Pin[e];
    const float2 qin = *(const float2*)&Qin[e];
    const float4 tr  = *(const float4*)&g_trig[e];   // cs0,sn0,cs1,sn1

    float2 rp, rq;
    rp.x = vm.x * (tr.x * U.x + tr.y * W.x) - pin.x;
    rq.x = vm.x * (tr.y * U.x - tr.x * W.x) - qin.x;
    rp.y = vm.y * (tr.z * U.y + tr.w * W.y) - pin.y;
    rq.y = vm.y * (tr.w * U.y - tr.z * W.y) - qin.y;

    *(float2*)&out[e]                = rp;
    *(float2*)&out[BATCH * NBUS + e] = rq;
}

// ---------------------------------------------------------------------------
extern "C" void kernel_launch(void* const* d_in, const int* in_sizes, int n_in,
                              void* d_out, int out_size) {
    const float* Vm  = (const float*)d_in[0];
    const float* Va  = (const float*)d_in[1];
    const float* Pin = (const float*)d_in[2];
    const float* Qin = (const float*)d_in[3];
    const float* Gm  = (const float*)d_in[4];
    const float* Bm  = (const float*)d_in[5];
    float* out = (float*)d_out;

    cudaFuncSetAttribute(gemm_kernel,
                         cudaFuncAttributeMaxDynamicSharedMemorySize, SMEM_TOTAL);

    prep_kernel<<<(BATCH * NBUS / 2 + 255) / 256, 256>>>(Vm, Va);
    gemm_kernel<<<NCTA, THREADS, SMEM_TOTAL>>>(Gm, Bm);
    epilogue_kernel<<<(BATCH * NBUS / 2 + 255) / 256, 256>>>(Vm, Pin, Qin, out);
}